// round 1
// baseline (speedup 1.0000x reference)
#include <cuda_runtime.h>

// ---------------- problem constants ----------------
#define HWT    80
#define NVOX   (HWT*HWT*HWT)      // 512000
#define CIN    32
#define DIM    48                  // heads*hd
#define NHEADS 8
#define HD     6
#define NMOT   (NHEADS*3*NVOX)     // 12288000
#define LN_EPS 1e-5f

// smem k-tile: [d=48][line=9][t+1 with halo: 82], plane stride 739 (odd -> conflict-free fill)
#define KS_PLANE 739
#define KS_WORDS (48*KS_PLANE)     // 35472 words
#define SMEM_B   (KS_WORDS*4)      // 141888 bytes

// ---------------- scratch (static device globals: no allocations allowed) ----
__device__ float g_q[(size_t)NVOX*DIM];
__device__ float g_k[(size_t)NVOX*DIM];
__device__ float g_partial[HWT*HWT];   // 6400 per-block score partials

// ---------------- kernel A: Linear(32->48) + LayerNorm for q and k ----------
__global__ __launch_bounds__(128) void proj_kernel(
    const float* __restrict__ F, const float* __restrict__ M,
    const float* __restrict__ Wm, const float* __restrict__ bias,
    const float* __restrict__ lnw, const float* __restrict__ lnb)
{
    __shared__ float sW[DIM*CIN];
    __shared__ float sB[DIM], sLW[DIM], sLB[DIM];
    __shared__ float ys[128*49];           // 49 pad: conflict-free row writes
    __shared__ float smu[128], srs[128];

    const int tid = threadIdx.x;
    for (int i = tid; i < DIM*CIN; i += 128) sW[i] = Wm[i];
    if (tid < DIM) { sB[tid] = bias[tid]; sLW[tid] = lnw[tid]; sLB[tid] = lnb[tid]; }
    __syncthreads();

    const float* __restrict__ src = blockIdx.y ? M : F;
    float* __restrict__ dst = blockIdx.y ? g_k : g_q;

    const int v = blockIdx.x * 128 + tid;

    float x[CIN];
#pragma unroll
    for (int c = 0; c < CIN; c++) x[c] = src[c*NVOX + v];

    float sum = 0.f, sq = 0.f;
    for (int d = 0; d < DIM; d++) {
        float acc = sB[d];
        const float4* wr = (const float4*)(sW + d*CIN);
#pragma unroll
        for (int c4 = 0; c4 < CIN/4; c4++) {
            float4 w4 = wr[c4];
            acc = fmaf(w4.x, x[4*c4+0], acc);
            acc = fmaf(w4.y, x[4*c4+1], acc);
            acc = fmaf(w4.z, x[4*c4+2], acc);
            acc = fmaf(w4.w, x[4*c4+3], acc);
        }
        ys[tid*49 + d] = acc;
        sum += acc;
        sq = fmaf(acc, acc, sq);
    }
    const float mu  = sum * (1.f/48.f);
    const float var = sq * (1.f/48.f) - mu*mu;
    smu[tid] = mu;
    srs[tid] = rsqrtf(var + LN_EPS);
    __syncthreads();

    // coalesced normalized write-out: [v][48] layout
    float* __restrict__ dchunk = dst + (size_t)blockIdx.x * (128*DIM);
    for (int i = tid; i < 128*DIM; i += 128) {
        const int lv = i / DIM;
        const int d  = i - lv*DIM;
        dchunk[i] = (ys[lv*49 + d] - smu[lv]) * srs[lv] * sLW[d] + sLB[d];
    }
}

// ---------------- kernel B: 27-neighbor QK + rpb + softmax + motion --------
__global__ __launch_bounds__(640, 1) void attn_kernel(
    const float* __restrict__ rpb, float* __restrict__ out)
{
    extern __shared__ float ks[];          // [48][9][82] plane-stride 739
    __shared__ float s_rpb[NHEADS*27];
    __shared__ float red[20];

    const int tid = threadIdx.x;
    const int hw = blockIdx.x;
    const int h = hw / HWT, w = hw % HWT;

    for (int i = tid; i < NHEADS*27; i += 640) s_rpb[i] = rpb[i];

    // zero t-halo slots (t=0 and t=81) for all d, all 9 lines
    for (int i = tid; i < DIM*9; i += 640) {
        const int d = i / 9, line = i % 9;
        ks[d*KS_PLANE + line*82 + 0]  = 0.f;
        ks[d*KS_PLANE + line*82 + 81] = 0.f;
    }
    // zero out-of-bounds neighbor lines entirely; fill valid lines from g_k
    for (int line = 0; line < 9; line++) {
        const int hh = h + line/3 - 1;
        const int ww = w + line%3 - 1;
        if (hh < 0 || hh >= HWT || ww < 0 || ww >= HWT) {
            for (int i = tid; i < DIM*HWT; i += 640) {
                const int d = i / HWT, t = i - d*HWT;
                ks[d*KS_PLANE + line*82 + t + 1] = 0.f;
            }
        } else {
            const float4* __restrict__ src =
                (const float4*)(g_k + (size_t)((hh*HWT + ww) * HWT) * DIM);
            for (int i = tid; i < HWT*(DIM/4); i += 640) {
                const float4 val = src[i];
                const int t  = i / (DIM/4);
                const int dq = i - t*(DIM/4);
                const int base = (4*dq)*KS_PLANE + line*82 + t + 1;
                ks[base             ] = val.x;
                ks[base +   KS_PLANE] = val.y;
                ks[base + 2*KS_PLANE] = val.z;
                ks[base + 3*KS_PLANE] = val.w;
            }
        }
    }
    __syncthreads();

    const int t    = tid % HWT;
    const int head = tid / HWT;
    const int v = (h*HWT + w)*HWT + t;

    float qv[HD];
    const float* __restrict__ qp = g_q + (size_t)v*DIM + head*HD;
#pragma unroll
    for (int d = 0; d < HD; d++) qv[d] = qp[d];

    float attn[27];
    const int hb = head*HD*KS_PLANE + t;
#pragma unroll
    for (int o = 0; o < 27; o++) {
        const int oi = o / 9, oj = (o / 3) % 3, ol = o % 3;
        const int line = oi*3 + oj;
        const float* __restrict__ kp = ks + hb + line*82 + ol;
        float a = 0.f;
#pragma unroll
        for (int d = 0; d < HD; d++)
            a = fmaf(qv[d], kp[d*KS_PLANE], a);
        attn[o] = a + s_rpb[head*27 + o];
    }

    float sc = attn[14];   // pre-softmax score channel (K^3/2 + 1)

    // softmax over 27
    float m = attn[0];
#pragma unroll
    for (int o = 1; o < 27; o++) m = fmaxf(m, attn[o]);
    float ssum = 0.f;
#pragma unroll
    for (int o = 0; o < 27; o++) { attn[o] = __expf(attn[o] - m); ssum += attn[o]; }
    const float inv = __fdividef(1.f, ssum);

    // expectation over displacements (i-1, j-1, l-1)
    float mx = 0.f, my = 0.f, mz = 0.f;
#pragma unroll
    for (int o = 0; o < 27; o++) {
        const int oi = o / 9, oj = (o / 3) % 3, ol = o % 3;
        if (oi == 2) mx += attn[o]; else if (oi == 0) mx -= attn[o];
        if (oj == 2) my += attn[o]; else if (oj == 0) my -= attn[o];
        if (ol == 2) mz += attn[o]; else if (ol == 0) mz -= attn[o];
    }

    out[(head*3 + 0)*NVOX + v] = mx * inv;
    out[(head*3 + 1)*NVOX + v] = my * inv;
    out[(head*3 + 2)*NVOX + v] = mz * inv;

    // deterministic block reduction of score channel
#pragma unroll
    for (int off = 16; off; off >>= 1) sc += __shfl_down_sync(0xffffffffu, sc, off);
    if ((tid & 31) == 0) red[tid >> 5] = sc;
    __syncthreads();
    if (tid < 32) {
        float v2 = (tid < 20) ? red[tid] : 0.f;
#pragma unroll
        for (int off = 16; off; off >>= 1) v2 += __shfl_down_sync(0xffffffffu, v2, off);
        if (tid == 0) g_partial[blockIdx.x] = v2;
    }
}

// ---------------- kernel C: deterministic final score reduction -------------
__global__ __launch_bounds__(256) void score_kernel(float* __restrict__ out)
{
    __shared__ double sd[256];
    const int tid = threadIdx.x;
    double a = 0.0;
    for (int i = tid; i < HWT*HWT; i += 256) a += (double)g_partial[i];
    sd[tid] = a;
    __syncthreads();
    for (int s = 128; s > 0; s >>= 1) {
        if (tid < s) sd[tid] += sd[tid + s];
        __syncthreads();
    }
    if (tid == 0) out[NMOT] = (float)(sd[0] * (1.0 / 4096000.0));
}

// ---------------- launch -----------------------------------------------------
extern "C" void kernel_launch(void* const* d_in, const int* in_sizes, int n_in,
                              void* d_out, int out_size)
{
    const float* F   = (const float*)d_in[0];
    const float* M   = (const float*)d_in[1];
    const float* Wm  = (const float*)d_in[2];
    const float* b   = (const float*)d_in[3];
    const float* lnw = (const float*)d_in[4];
    const float* lnb = (const float*)d_in[5];
    const float* rpb = (const float*)d_in[6];
    float* out = (float*)d_out;

    cudaFuncSetAttribute(attn_kernel, cudaFuncAttributeMaxDynamicSharedMemorySize, SMEM_B);

    proj_kernel<<<dim3(NVOX/128, 2, 1), 128>>>(F, M, Wm, b, lnw, lnb);
    attn_kernel<<<HWT*HWT, 640, SMEM_B>>>(rpb, out);
    if (out_size > NMOT) score_kernel<<<1, 256>>>(out);
}

// round 2
// speedup vs baseline: 1.1764x; 1.1764x over previous
#include <cuda_runtime.h>

// ---------------- problem constants ----------------
#define HWT    80
#define NVOX   (HWT*HWT*HWT)      // 512000
#define CIN    32
#define DIM    48                  // heads*hd
#define NHEADS 8
#define HD     6
#define NMOT   (NHEADS*3*NVOX)     // 12288000
#define LN_EPS 1e-5f

// attn smem: per-head k tile [6 d][18 lines][82 t]
#define DSTRIDE 1476               // 18*82
#define KS_WORDS (HD*DSTRIDE)      // 8856
#define SMEM_ATTN (KS_WORDS*4)     // 35424 B

// ---------------- packed fp32x2 helpers (sm_103a) ----------------
#define FMA_F32X2(d, a, b, c) \
    asm("fma.rn.f32x2 %0, %1, %2, %3;" : "=l"(d) : "l"(a), "l"(b), "l"(c))
#define PACK_F32X2(out, lo, hi) \
    asm("mov.b64 %0, {%1, %2};" : "=l"(out) : "f"(lo), "f"(hi))
#define UNPACK_F32X2(lo, hi, in) \
    asm("mov.b64 {%0, %1}, %2;" : "=f"(lo), "=f"(hi) : "l"(in))

// ---------------- scratch (static device globals) ----------------
// d-major layout: [48][NVOX]
__device__ float g_q[(size_t)DIM*NVOX];
__device__ float g_k[(size_t)DIM*NVOX];
__device__ float g_partial[1600*NHEADS];   // 12800 per-block score partials

// ============ kernel A: Linear(32->48) + LayerNorm, 2 voxels/thread =========
__global__ __launch_bounds__(128) void proj_kernel(
    const float* __restrict__ F, const float* __restrict__ M,
    const float* __restrict__ Wm, const float* __restrict__ bias,
    const float* __restrict__ lnw, const float* __restrict__ lnb)
{
    __shared__ float sWt[CIN*DIM];   // transposed: [c][d], d contiguous
    __shared__ float sB[DIM], sLW[DIM], sLB[DIM];

    const int tid = threadIdx.x;
    for (int i = tid; i < DIM*CIN; i += 128) {
        const int d = i / CIN, c = i - d*CIN;
        sWt[c*DIM + d] = Wm[i];
    }
    if (tid < DIM) { sB[tid] = bias[tid]; sLW[tid] = lnw[tid]; sLB[tid] = lnb[tid]; }
    __syncthreads();

    const float* __restrict__ src = blockIdx.y ? M : F;
    float* __restrict__ dst = blockIdx.y ? g_k : g_q;

    const int v0 = blockIdx.x * 256 + tid;
    const int v1 = v0 + 128;

    // packed accumulators over d-pairs, two voxels
    unsigned long long acc0[DIM/2], acc1[DIM/2];
#pragma unroll
    for (int j = 0; j < DIM/2; j++) {
        unsigned long long b2;
        PACK_F32X2(b2, sB[2*j], sB[2*j+1]);
        acc0[j] = b2; acc1[j] = b2;
    }

#pragma unroll 4
    for (int c = 0; c < CIN; c++) {
        const float x0 = src[(size_t)c*NVOX + v0];
        const float x1 = src[(size_t)c*NVOX + v1];
        unsigned long long xx0, xx1;
        PACK_F32X2(xx0, x0, x0);
        PACK_F32X2(xx1, x1, x1);
        const ulonglong2* __restrict__ wr = (const ulonglong2*)(sWt + c*DIM);
#pragma unroll
        for (int j2 = 0; j2 < DIM/4; j2++) {
            const ulonglong2 w2 = wr[j2];
            FMA_F32X2(acc0[2*j2  ], w2.x, xx0, acc0[2*j2  ]);
            FMA_F32X2(acc0[2*j2+1], w2.y, xx0, acc0[2*j2+1]);
            FMA_F32X2(acc1[2*j2  ], w2.x, xx1, acc1[2*j2  ]);
            FMA_F32X2(acc1[2*j2+1], w2.y, xx1, acc1[2*j2+1]);
        }
    }

    // layernorm + d-major coalesced writeout, per voxel
#pragma unroll
    for (int vv = 0; vv < 2; vv++) {
        const unsigned long long* acc = vv ? acc1 : acc0;
        const int v = vv ? v1 : v0;
        float sum = 0.f, sq = 0.f;
#pragma unroll
        for (int j = 0; j < DIM/2; j++) {
            float a, b;
            UNPACK_F32X2(a, b, acc[j]);
            sum += a + b;
            sq = fmaf(a, a, sq);
            sq = fmaf(b, b, sq);
        }
        const float mu = sum * (1.f/48.f);
        const float rs = rsqrtf(sq * (1.f/48.f) - mu*mu + LN_EPS);
#pragma unroll
        for (int j = 0; j < DIM/2; j++) {
            float a, b;
            UNPACK_F32X2(a, b, acc[j]);
            dst[(size_t)(2*j  )*NVOX + v] = (a - mu) * rs * sLW[2*j  ] + sLB[2*j  ];
            dst[(size_t)(2*j+1)*NVOX + v] = (b - mu) * rs * sLW[2*j+1] + sLB[2*j+1];
        }
    }
}

// ======== kernel B: per-(head, 4w-strip) 27-neighbor attention ==============
__global__ __launch_bounds__(320, 3) void attn_kernel(
    const float* __restrict__ rpb, float* __restrict__ out)
{
    extern __shared__ float ks[];          // [6 d][18 lines][82 t]
    __shared__ float s_rpb[27];
    __shared__ float red[10];

    const int tid  = threadIdx.x;
    const int bx   = blockIdx.x;           // 0..1599
    const int head = blockIdx.y;            // 0..7
    const int h    = bx / 20;
    const int w0   = (bx - h*20) * 4;
    const int hd6  = head * HD;

    if (tid < 27) s_rpb[tid] = rpb[head*27 + tid];

    // zero t-halo slots
    for (int i = tid; i < HD*18*2; i += 320) {
        const int d = i / 36, r = i - d*36;
        const int line = r >> 1, e = r & 1;
        ks[d*DSTRIDE + line*82 + (e ? 81 : 0)] = 0.f;
    }
    // coalesced d-major fill: 6 d x 18 lines x 80 t
    for (int i = tid; i < HD*18*HWT; i += 320) {
        const int d = i / (18*HWT);
        const int r = i - d*(18*HWT);
        const int line = r / HWT;
        const int t = r - line*HWT;
        const int lh = h + line/6 - 1;
        const int lw = w0 + line%6 - 1;
        float val = 0.f;
        if (lh >= 0 && lh < HWT && lw >= 0 && lw < HWT)
            val = g_k[(size_t)(hd6 + d)*NVOX + (lh*HWT + lw)*HWT + t];
        ks[d*DSTRIDE + line*82 + t + 1] = val;
    }
    __syncthreads();

    const int t  = tid % HWT;
    const int wl = tid / HWT;               // 0..3
    const int w  = w0 + wl;
    const int v  = (h*HWT + w)*HWT + t;

    float qv[HD];
#pragma unroll
    for (int d = 0; d < HD; d++)
        qv[d] = g_q[(size_t)(hd6 + d)*NVOX + v];

    float attn[27];
#pragma unroll
    for (int o = 0; o < 27; o++) {
        const int oi = o / 9, oj = (o / 3) % 3, ol = o % 3;
        const int line = oi*6 + wl + oj;
        const float* __restrict__ kp = ks + line*82 + t + ol;
        float a = 0.f;
#pragma unroll
        for (int d = 0; d < HD; d++)
            a = fmaf(qv[d], kp[d*DSTRIDE], a);
        attn[o] = a + s_rpb[o];
    }

    float sc = attn[14];   // pre-softmax score channel (K^3/2 + 1)

    // softmax over 27
    float m = attn[0];
#pragma unroll
    for (int o = 1; o < 27; o++) m = fmaxf(m, attn[o]);
    float ssum = 0.f;
#pragma unroll
    for (int o = 0; o < 27; o++) { attn[o] = __expf(attn[o] - m); ssum += attn[o]; }
    const float inv = __fdividef(1.f, ssum);

    // expectation over displacements
    float mx = 0.f, my = 0.f, mz = 0.f;
#pragma unroll
    for (int o = 0; o < 27; o++) {
        const int oi = o / 9, oj = (o / 3) % 3, ol = o % 3;
        if (oi == 2) mx += attn[o]; else if (oi == 0) mx -= attn[o];
        if (oj == 2) my += attn[o]; else if (oj == 0) my -= attn[o];
        if (ol == 2) mz += attn[o]; else if (ol == 0) mz -= attn[o];
    }

    out[(size_t)(head*3 + 0)*NVOX + v] = mx * inv;
    out[(size_t)(head*3 + 1)*NVOX + v] = my * inv;
    out[(size_t)(head*3 + 2)*NVOX + v] = mz * inv;

    // deterministic block reduction of score channel
#pragma unroll
    for (int off = 16; off; off >>= 1) sc += __shfl_down_sync(0xffffffffu, sc, off);
    if ((tid & 31) == 0) red[tid >> 5] = sc;
    __syncthreads();
    if (tid < 32) {
        float v2 = (tid < 10) ? red[tid] : 0.f;
#pragma unroll
        for (int off = 16; off; off >>= 1) v2 += __shfl_down_sync(0xffffffffu, v2, off);
        if (tid == 0) g_partial[head*1600 + bx] = v2;
    }
}

// ---------------- kernel C: deterministic final score reduction -------------
__global__ __launch_bounds__(256) void score_kernel(float* __restrict__ out)
{
    __shared__ double sd[256];
    const int tid = threadIdx.x;
    double a = 0.0;
    for (int i = tid; i < 1600*NHEADS; i += 256) a += (double)g_partial[i];
    sd[tid] = a;
    __syncthreads();
    for (int s = 128; s > 0; s >>= 1) {
        if (tid < s) sd[tid] += sd[tid + s];
        __syncthreads();
    }
    if (tid == 0) out[NMOT] = (float)(sd[0] * (1.0 / 4096000.0));
}

// ---------------- launch -----------------------------------------------------
extern "C" void kernel_launch(void* const* d_in, const int* in_sizes, int n_in,
                              void* d_out, int out_size)
{
    const float* F   = (const float*)d_in[0];
    const float* M   = (const float*)d_in[1];
    const float* Wm  = (const float*)d_in[2];
    const float* b   = (const float*)d_in[3];
    const float* lnw = (const float*)d_in[4];
    const float* lnb = (const float*)d_in[5];
    const float* rpb = (const float*)d_in[6];
    float* out = (float*)d_out;

    cudaFuncSetAttribute(attn_kernel, cudaFuncAttributeMaxDynamicSharedMemorySize, SMEM_ATTN);

    proj_kernel<<<dim3(NVOX/256, 2, 1), 128>>>(F, M, Wm, b, lnw, lnb);
    attn_kernel<<<dim3(1600, NHEADS, 1), 320, SMEM_ATTN>>>(rpb, out);
    if (out_size > NMOT) score_kernel<<<1, 256>>>(out);
}